// round 5
// baseline (speedup 1.0000x reference)
#include <cuda_runtime.h>
#include <cuda_bf16.h>
#include <cstdint>

// ---------------- problem constants ----------------
#define NN     8192
#define INF    128
#define HID    512
#define OUTF   256
#define H3     (3*HID)     // 1536
#define O3     (3*OUTF)    // 768

// ---------------- GEMM tiling ----------------
#define BM 128
#define BN 256
#define BK 32
#define ST 4               // pipeline stages
#define ASTR (BK + 8)      // 40 bf16 per A smem row
#define BSTR (BN + 8)      // 264 bf16 per B smem row
#define AS_SIZE (BM * ASTR)   // 5120 elems
#define BS_SIZE (BK * BSTR)   // 8448 elems
#define SMEM_ELEMS (ST * 2 * (AS_SIZE + BS_SIZE))   // 108544
#define SMEM_BYTES (SMEM_ELEMS * 2)                 // 217088

// ---------------- device scratch: everything pre-split into bf16 hi/lo ----------------
__device__ __nv_bfloat16 g_adj_h[(long)NN * NN], g_adj_l[(long)NN * NN];
__device__ __nv_bfloat16 g_x_h [NN * INF],      g_x_l [NN * INF];
__device__ __nv_bfloat16 g_w1_h[3 * INF * HID], g_w1_l[3 * INF * HID];
__device__ __nv_bfloat16 g_w2_h[3 * H3 * OUTF], g_w2_l[3 * H3 * OUTF];
__device__ __nv_bfloat16 g_wf_h[O3 * OUTF],     g_wf_l[O3 * OUTF];
__device__ __nv_bfloat16 g_hh  [NN * H3],       g_hl  [NN * H3];
__device__ __nv_bfloat16 g_zth [NN * 1024],     g_ztl [NN * 1024];
__device__ __nv_bfloat16 g_u1h [NN * HID],      g_u1l [NN * HID];
__device__ __nv_bfloat16 g_gh  [NN * O3],       g_gl  [NN * O3];
__device__ __nv_bfloat16 g_z2h [NN * 512],      g_z2l [NN * 512];
__device__ __nv_bfloat16 g_u2h [NN * OUTF],     g_u2l [NN * OUTF];
__device__ float g_sc[H3], g_sh[H3];

// ---------------- helpers ----------------
__device__ __forceinline__ void ldsm_x4(uint32_t* r, uint32_t addr) {
    asm volatile("ldmatrix.sync.aligned.m8n8.x4.shared.b16 {%0,%1,%2,%3}, [%4];"
                 : "=r"(r[0]), "=r"(r[1]), "=r"(r[2]), "=r"(r[3]) : "r"(addr));
}
__device__ __forceinline__ void ldsm_x4_t(uint32_t* r, uint32_t addr) {
    asm volatile("ldmatrix.sync.aligned.m8n8.x4.trans.shared.b16 {%0,%1,%2,%3}, [%4];"
                 : "=r"(r[0]), "=r"(r[1]), "=r"(r[2]), "=r"(r[3]) : "r"(addr));
}
__device__ __forceinline__ void mma16816(float* c, const uint32_t* a, const uint32_t* b) {
    asm volatile("mma.sync.aligned.m16n8k16.row.col.f32.bf16.bf16.f32 "
                 "{%0,%1,%2,%3}, {%4,%5,%6,%7}, {%8,%9}, {%0,%1,%2,%3};"
                 : "+f"(c[0]), "+f"(c[1]), "+f"(c[2]), "+f"(c[3])
                 : "r"(a[0]), "r"(a[1]), "r"(a[2]), "r"(a[3]), "r"(b[0]), "r"(b[1]));
}
__device__ __forceinline__ void cpasync16(uint32_t dst, const void* src) {
    asm volatile("cp.async.cg.shared.global [%0], [%1], 16;" :: "r"(dst), "l"(src));
}
__device__ __forceinline__ void cp_commit() { asm volatile("cp.async.commit_group;"); }
__device__ __forceinline__ void cp_wait2()  { asm volatile("cp.async.wait_group 2;"); }

// (a,b) fp32 -> hi/lo bf16x2 packed as uint32
__device__ __forceinline__ void split2(float a, float b, uint32_t& hi, uint32_t& lo) {
    __nv_bfloat162 h = __floats2bfloat162_rn(a, b);
    float2 f = __bfloat1622float2(h);
    __nv_bfloat162 l = __floats2bfloat162_rn(a - f.x, b - f.y);
    hi = *reinterpret_cast<uint32_t*>(&h);
    lo = *reinterpret_cast<uint32_t*>(&l);
}

// ---------------- fp32 -> split bf16 conversion (4 elems/thread) ----------------
__global__ void convert_split(const float* __restrict__ in,
                              __nv_bfloat16* __restrict__ oh,
                              __nv_bfloat16* __restrict__ ol, long n)
{
    long i = ((long)blockIdx.x * blockDim.x + threadIdx.x) * 4;
    if (i >= n) return;
    float4 v = *reinterpret_cast<const float4*>(in + i);
    uint32_t h0, l0, h1, l1;
    split2(v.x, v.y, h0, l0);
    split2(v.z, v.w, h1, l1);
    *reinterpret_cast<uint2*>(oh + i) = make_uint2(h0, h1);
    *reinterpret_cast<uint2*>(ol + i) = make_uint2(l0, l1);
}

// ---------------- split-bf16 (fp32-accurate) GEMM, 128x256 tile, cp.async x4 -------
// C[M,N] = (Ah+Al)[M,K] @ (Bh+Bl)[K,N] (+bias). Row-major, element strides.
// B segmented: col c at B + (c/seg)*segstride + k*ldb + (c%seg).
// Epilogue: if outF -> fp32 row-major; else split bf16, cols [0,split)->o0, rest->o1.
__global__ __launch_bounds__(256, 1) void gemm_bf16split(
    const __nv_bfloat16* __restrict__ Ah, const __nv_bfloat16* __restrict__ Al, int lda,
    const __nv_bfloat16* __restrict__ Bh, const __nv_bfloat16* __restrict__ Bl,
    int ldb, int seg, long segstride,
    const float* __restrict__ bias,
    __nv_bfloat16* __restrict__ o0h, __nv_bfloat16* __restrict__ o0l, int ld0, int split,
    __nv_bfloat16* __restrict__ o1h, __nv_bfloat16* __restrict__ o1l, int ld1,
    float* __restrict__ outF, int ldF,
    int K)
{
    extern __shared__ __nv_bfloat16 smem[];
    __nv_bfloat16* As_h = smem;                       // ST*AS_SIZE
    __nv_bfloat16* As_l = As_h + ST * AS_SIZE;
    __nv_bfloat16* Bs_h = As_l + ST * AS_SIZE;
    __nv_bfloat16* Bs_l = Bs_h + ST * BS_SIZE;

    const int tid  = threadIdx.x;
    const int lane = tid & 31;
    const int warp = tid >> 5;
    const int wm   = warp >> 2;   // 0..1 : 64-row slab
    const int wn   = warp & 3;    // 0..3 : 64-col slab

    const int m0 = blockIdx.y * BM;
    const int n0 = blockIdx.x * BN;

    const int jseg = n0 / seg;
    const __nv_bfloat16* Bbh = Bh + (long)jseg * segstride + (n0 - jseg * seg);
    const __nv_bfloat16* Bbl = Bl + (long)jseg * segstride + (n0 - jseg * seg);

    // staging coords: A 128x32 = 512 chunks (2/thread), B 32x256 = 1024 chunks (4/thread)
    const int c0 = tid, c1 = tid + 256;
    const int ar0 = c0 >> 2, aq0 = (c0 & 3) << 3;
    const int ar1 = c1 >> 2, aq1 = (c1 & 3) << 3;
    int brr[4], bqq[4];
#pragma unroll
    for (int i = 0; i < 4; i++) {
        int c = tid + 256 * i;
        brr[i] = c >> 5;           // 0..31 row
        bqq[i] = (c & 31) << 3;    // col chunk start
    }

#define ISSUE(s, k0) do {                                                              \
    uint32_t d;                                                                        \
    d = (uint32_t)__cvta_generic_to_shared(As_h + (s)*AS_SIZE + ar0*ASTR + aq0);       \
    cpasync16(d, Ah + (long)(m0 + ar0) * lda + (k0) + aq0);                            \
    d = (uint32_t)__cvta_generic_to_shared(As_h + (s)*AS_SIZE + ar1*ASTR + aq1);       \
    cpasync16(d, Ah + (long)(m0 + ar1) * lda + (k0) + aq1);                            \
    d = (uint32_t)__cvta_generic_to_shared(As_l + (s)*AS_SIZE + ar0*ASTR + aq0);       \
    cpasync16(d, Al + (long)(m0 + ar0) * lda + (k0) + aq0);                            \
    d = (uint32_t)__cvta_generic_to_shared(As_l + (s)*AS_SIZE + ar1*ASTR + aq1);       \
    cpasync16(d, Al + (long)(m0 + ar1) * lda + (k0) + aq1);                            \
    _Pragma("unroll") for (int i = 0; i < 4; i++) {                                    \
        d = (uint32_t)__cvta_generic_to_shared(Bs_h + (s)*BS_SIZE + brr[i]*BSTR + bqq[i]); \
        cpasync16(d, Bbh + (long)((k0) + brr[i]) * ldb + bqq[i]);                      \
        d = (uint32_t)__cvta_generic_to_shared(Bs_l + (s)*BS_SIZE + brr[i]*BSTR + bqq[i]); \
        cpasync16(d, Bbl + (long)((k0) + brr[i]) * ldb + bqq[i]);                      \
    }                                                                                  \
} while (0)

    float acc[4][8][4];
#pragma unroll
    for (int i = 0; i < 4; i++)
#pragma unroll
        for (int j = 0; j < 8; j++)
#pragma unroll
            for (int k = 0; k < 4; k++) acc[i][j][k] = 0.f;

    const int KT = K >> 5;

    // prologue: fill ST-1 stages
#pragma unroll
    for (int s = 0; s < ST - 1; s++) {
        ISSUE(s, s << 5);
        cp_commit();
    }

    for (int kt = 0; kt < KT; kt++) {
        cp_wait2();
        __syncthreads();
        const int stg = kt & (ST - 1);

#pragma unroll
        for (int ks = 0; ks < 2; ks++) {
            uint32_t ah[4][4], al[4][4];
            const int arow = wm * 64 + (lane & 15);
            const int acol = ks * 16 + ((lane >> 4) << 3);
#pragma unroll
            for (int mt = 0; mt < 4; mt++) {
                int idx = stg * AS_SIZE + (arow + mt * 16) * ASTR + acol;
                ldsm_x4(ah[mt], (uint32_t)__cvta_generic_to_shared(As_h + idx));
                ldsm_x4(al[mt], (uint32_t)__cvta_generic_to_shared(As_l + idx));
            }
            const int brow  = ks * 16 + (lane & 15);
            const int bcolb = wn * 64 + ((lane >> 4) << 3);
#pragma unroll
            for (int nt2 = 0; nt2 < 4; nt2++) {
                int idx = stg * BS_SIZE + brow * BSTR + bcolb + nt2 * 16;
                uint32_t rh[4], rl[4];
                ldsm_x4_t(rh, (uint32_t)__cvta_generic_to_shared(Bs_h + idx));
                ldsm_x4_t(rl, (uint32_t)__cvta_generic_to_shared(Bs_l + idx));
                // rh/rl: [0,1] = cols nt2*16..+8, [2,3] = +8..+16
#pragma unroll
                for (int half = 0; half < 2; half++) {
                    const int nt = nt2 * 2 + half;
                    uint32_t bh2[2] = { rh[half * 2], rh[half * 2 + 1] };
                    uint32_t bl2[2] = { rl[half * 2], rl[half * 2 + 1] };
#pragma unroll
                    for (int mt = 0; mt < 4; mt++) {
                        mma16816(acc[mt][nt], ah[mt], bh2);   // hi*hi
                        mma16816(acc[mt][nt], ah[mt], bl2);   // hi*lo
                        mma16816(acc[mt][nt], al[mt], bh2);   // lo*hi
                    }
                }
            }
        }

        const int kn = kt + ST - 1;
        if (kn < KT) {
            // writes stage (kt-1)%ST: consumed before the __syncthreads above.
            ISSUE(kn & (ST - 1), kn << 5);
        }
        cp_commit();
    }
#undef ISSUE

    // ---- epilogue ----
#pragma unroll
    for (int mt = 0; mt < 4; mt++) {
        const int r0 = m0 + wm * 64 + mt * 16 + (lane >> 2);
#pragma unroll
        for (int nt = 0; nt < 8; nt++) {
            const int gc = n0 + wn * 64 + nt * 8 + ((lane & 3) << 1);
            float2 v0 = make_float2(acc[mt][nt][0], acc[mt][nt][1]);
            float2 v1 = make_float2(acc[mt][nt][2], acc[mt][nt][3]);
            if (bias) {
                float b0 = bias[gc], b1v = bias[gc + 1];
                v0.x += b0; v0.y += b1v; v1.x += b0; v1.y += b1v;
            }
            if (outF) {
                *reinterpret_cast<float2*>(outF + (long)r0 * ldF + gc) = v0;
                *reinterpret_cast<float2*>(outF + (long)(r0 + 8) * ldF + gc) = v1;
            } else {
                __nv_bfloat16 *ph, *pl;
                int col;
                if (gc < split) { ph = o0h; pl = o0l; col = gc;          }
                else            { ph = o1h; pl = o1l; col = gc - split;  }
                const int ld = (gc < split) ? ld0 : ld1;
                uint32_t h0, l0, h1, l1;
                split2(v0.x, v0.y, h0, l0);
                split2(v1.x, v1.y, h1, l1);
                *reinterpret_cast<uint32_t*>(ph + (long)r0 * ld + col)       = h0;
                *reinterpret_cast<uint32_t*>(pl + (long)r0 * ld + col)       = l0;
                *reinterpret_cast<uint32_t*>(ph + (long)(r0 + 8) * ld + col) = h1;
                *reinterpret_cast<uint32_t*>(pl + (long)(r0 + 8) * ld + col) = l1;
            }
        }
    }
}

// ---------------- batchnorm (training-mode stats) on split h ----------------
__global__ void bn_stats(const __nv_bfloat16* __restrict__ hh,
                         const __nv_bfloat16* __restrict__ hl,
                         const float* __restrict__ gamma,
                         const float* __restrict__ beta,
                         float* __restrict__ sc, float* __restrict__ sh)
{
    __shared__ float ss[16][32], sq[16][32];
    const int c   = threadIdx.x & 31;
    const int col = blockIdx.x * 32 + c;
    const int rg  = threadIdx.x >> 5;
    float s = 0.f, s2 = 0.f;
    for (int r = rg; r < NN; r += 16) {
        long i = (long)r * H3 + col;
        float v = __bfloat162float(hh[i]) + __bfloat162float(hl[i]);
        s += v; s2 += v * v;
    }
    ss[rg][c] = s; sq[rg][c] = s2;
    __syncthreads();
    if (rg == 0) {
#pragma unroll
        for (int k = 1; k < 16; k++) { s += ss[k][c]; s2 += sq[k][c]; }
        const float mean = s * (1.f / NN);
        const float var  = s2 * (1.f / NN) - mean * mean;
        const float scale = gamma[col] * rsqrtf(var + 1e-5f);
        sc[col] = scale;
        sh[col] = beta[col] - mean * scale;
    }
}

// h = relu(h*sc + sh), in-place on split rep, 4 elems/thread
__global__ void bn_apply_relu(__nv_bfloat16* __restrict__ hh,
                              __nv_bfloat16* __restrict__ hl,
                              const float* __restrict__ sc,
                              const float* __restrict__ sh)
{
    const long i = ((long)blockIdx.x * blockDim.x + threadIdx.x) * 4;
    uint2 uh = *reinterpret_cast<uint2*>(hh + i);
    uint2 ul = *reinterpret_cast<uint2*>(hl + i);
    float2 a01 = __bfloat1622float2(*reinterpret_cast<__nv_bfloat162*>(&uh.x));
    float2 a23 = __bfloat1622float2(*reinterpret_cast<__nv_bfloat162*>(&uh.y));
    float2 b01 = __bfloat1622float2(*reinterpret_cast<__nv_bfloat162*>(&ul.x));
    float2 b23 = __bfloat1622float2(*reinterpret_cast<__nv_bfloat162*>(&ul.y));
    const int c = (int)(i % H3);
    float y0 = fmaxf(0.f, (a01.x + b01.x) * sc[c]     + sh[c]);
    float y1 = fmaxf(0.f, (a01.y + b01.y) * sc[c + 1] + sh[c + 1]);
    float y2 = fmaxf(0.f, (a23.x + b23.x) * sc[c + 2] + sh[c + 2]);
    float y3 = fmaxf(0.f, (a23.y + b23.y) * sc[c + 3] + sh[c + 3]);
    uint32_t h0, l0, h1, l1;
    split2(y0, y1, h0, l0);
    split2(y2, y3, h1, l1);
    *reinterpret_cast<uint2*>(hh + i) = make_uint2(h0, h1);
    *reinterpret_cast<uint2*>(hl + i) = make_uint2(l0, l1);
}

// ---------------- launcher ----------------
struct Ptrs {
    __nv_bfloat16 *adjh, *adjl, *xh, *xl, *w1h, *w1l, *w2h, *w2l, *wfh, *wfl;
    __nv_bfloat16 *hh, *hl, *zth, *ztl, *u1h, *u1l, *gh, *gl, *z2h, *z2l, *u2h, *u2l;
    float *sc, *sh;
};
static void get_ptrs(Ptrs& p) {
    cudaGetSymbolAddress((void**)&p.adjh, g_adj_h); cudaGetSymbolAddress((void**)&p.adjl, g_adj_l);
    cudaGetSymbolAddress((void**)&p.xh, g_x_h);     cudaGetSymbolAddress((void**)&p.xl, g_x_l);
    cudaGetSymbolAddress((void**)&p.w1h, g_w1_h);   cudaGetSymbolAddress((void**)&p.w1l, g_w1_l);
    cudaGetSymbolAddress((void**)&p.w2h, g_w2_h);   cudaGetSymbolAddress((void**)&p.w2l, g_w2_l);
    cudaGetSymbolAddress((void**)&p.wfh, g_wf_h);   cudaGetSymbolAddress((void**)&p.wfl, g_wf_l);
    cudaGetSymbolAddress((void**)&p.hh, g_hh);      cudaGetSymbolAddress((void**)&p.hl, g_hl);
    cudaGetSymbolAddress((void**)&p.zth, g_zth);    cudaGetSymbolAddress((void**)&p.ztl, g_ztl);
    cudaGetSymbolAddress((void**)&p.u1h, g_u1h);    cudaGetSymbolAddress((void**)&p.u1l, g_u1l);
    cudaGetSymbolAddress((void**)&p.gh, g_gh);      cudaGetSymbolAddress((void**)&p.gl, g_gl);
    cudaGetSymbolAddress((void**)&p.z2h, g_z2h);    cudaGetSymbolAddress((void**)&p.z2l, g_z2l);
    cudaGetSymbolAddress((void**)&p.u2h, g_u2h);    cudaGetSymbolAddress((void**)&p.u2l, g_u2l);
    cudaGetSymbolAddress((void**)&p.sc, g_sc);      cudaGetSymbolAddress((void**)&p.sh, g_sh);
}

static inline void run_conv(const float* in, __nv_bfloat16* oh, __nv_bfloat16* ol, long n) {
    convert_split<<<(int)(n / 1024), 256>>>(in, oh, ol, n);
}

static inline void run_gemm(const __nv_bfloat16* Ah, const __nv_bfloat16* Al, int lda,
                            const __nv_bfloat16* Bh, const __nv_bfloat16* Bl,
                            int ldb, int seg, long segstride,
                            const float* bias,
                            __nv_bfloat16* o0h, __nv_bfloat16* o0l, int ld0, int split,
                            __nv_bfloat16* o1h, __nv_bfloat16* o1l, int ld1,
                            float* outF, int ldF,
                            int M, int N, int K)
{
    dim3 grid(N / BN, M / BM);
    gemm_bf16split<<<grid, 256, SMEM_BYTES>>>(Ah, Al, lda, Bh, Bl, ldb, seg, segstride,
                                              bias, o0h, o0l, ld0, split, o1h, o1l, ld1,
                                              outF, ldF, K);
}

extern "C" void kernel_launch(void* const* d_in, const int* in_sizes, int n_in,
                              void* d_out, int out_size)
{
    const float* x     = (const float*)d_in[0];
    const float* adj   = (const float*)d_in[1];
    const float* W1    = (const float*)d_in[2];
    const float* b1    = (const float*)d_in[3];
    const float* W2    = (const float*)d_in[4];
    const float* b2    = (const float*)d_in[5];
    const float* gamma = (const float*)d_in[6];
    const float* beta  = (const float*)d_in[7];
    const float* Wf    = (const float*)d_in[8];
    const float* bf    = (const float*)d_in[9];
    float* out = (float*)d_out;

    Ptrs p; get_ptrs(p);
    cudaFuncSetAttribute(gemm_bf16split,
                         cudaFuncAttributeMaxDynamicSharedMemorySize, SMEM_BYTES);

    // ---- pre-split all external operands ----
    run_conv(adj, p.adjh, p.adjl, (long)NN * NN);
    run_conv(x,   p.xh,   p.xl,   (long)NN * INF);
    run_conv(W1,  p.w1h,  p.w1l,  3L * INF * HID);
    run_conv(W2,  p.w2h,  p.w2l,  3L * H3 * OUTF);
    run_conv(Wf,  p.wfh,  p.wfl,  (long)O3 * OUTF);

    // ---- layer 1 ----
    // G1: x @ [W1_0|W1_1|W1_2] + b1 -> hop0 into h[:,0:512], hops1/2 into ZT
    run_gemm(p.xh, p.xl, INF, p.w1h, p.w1l, HID, HID, (long)INF * HID, b1,
             p.hh, p.hl, H3, HID, p.zth, p.ztl, 1024, nullptr, 0, NN, H3, INF);
    // G2: adj @ ZT -> hop1 into h[:,512:1024], hop2-intermediate into U1
    run_gemm(p.adjh, p.adjl, NN, p.zth, p.ztl, 1024, 1024, 0, nullptr,
             p.hh + HID, p.hl + HID, H3, HID, p.u1h, p.u1l, HID, nullptr, 0, NN, 1024, NN);
    // G3: adj @ U1 -> hop2 into h[:,1024:1536]
    run_gemm(p.adjh, p.adjl, NN, p.u1h, p.u1l, HID, HID, 0, nullptr,
             p.hh + 2 * HID, p.hl + 2 * HID, H3, HID, nullptr, nullptr, 0, nullptr, 0,
             NN, HID, NN);

    // ---- batchnorm + relu (on split rep) ----
    bn_stats<<<H3 / 32, 512>>>(p.hh, p.hl, gamma, beta, p.sc, p.sh);
    bn_apply_relu<<<(NN * H3 / 4) / 256, 256>>>(p.hh, p.hl, p.sc, p.sh);

    // ---- layer 2 ----
    // G4: h @ [W2_0|W2_1|W2_2] + b2 -> hop0 into g[:,0:256], hops1/2 into Z2
    run_gemm(p.hh, p.hl, H3, p.w2h, p.w2l, OUTF, OUTF, (long)H3 * OUTF, b2,
             p.gh, p.gl, O3, OUTF, p.z2h, p.z2l, 512, nullptr, 0, NN, O3, H3);
    // G5: adj @ Z2 -> hop1 into g[:,256:512], hop2-intermediate into U2
    run_gemm(p.adjh, p.adjl, NN, p.z2h, p.z2l, 512, 512, 0, nullptr,
             p.gh + OUTF, p.gl + OUTF, O3, OUTF, p.u2h, p.u2l, OUTF, nullptr, 0,
             NN, 512, NN);
    // G6: adj @ U2 -> hop2 into g[:,512:768]
    run_gemm(p.adjh, p.adjl, NN, p.u2h, p.u2l, OUTF, OUTF, 0, nullptr,
             p.gh + 2 * OUTF, p.gl + 2 * OUTF, O3, OUTF, nullptr, nullptr, 0, nullptr, 0,
             NN, OUTF, NN);

    // ---- final linear: g @ Wf + bf -> fp32 out ----
    run_gemm(p.gh, p.gl, O3, p.wfh, p.wfl, OUTF, OUTF, 0, bf,
             nullptr, nullptr, 0, OUTF, nullptr, nullptr, 0, out, OUTF, NN, OUTF, O3);
}